// round 10
// baseline (speedup 1.0000x reference)
#include <cuda_runtime.h>
#include <cuda_fp16.h>
#include <math.h>
#include <stdint.h>

// ---------------------------------------------------------------------------
// HFLongFormerSelfAttentionBlock on GB300 (sm_103 base PTX target -> mma.sync)
// R6: revert R5 experiments (exp_fast, f16-acc). Single-term fp16 GEMMs:
//     out = fp16(x) @ fp16(w)^T with fp32 accumulation (halves MMA count
//     vs R4's 2-term weight split; predicted rel_err ~2.4e-4).
// ---------------------------------------------------------------------------

#define NEGF (-3.4028234663852886e38f)

// ---------------- scratch (device globals; no allocation allowed) ----------
__device__ float g_q[4194304];     // (B,NH,S0,HD)
__device__ float g_k[4194304];
__device__ float g_v[4194304];
__device__ float g_attn[4194304];  // (B*S0, H)
__device__ float g_y[4194304];     // LN output fp32
__device__ __half g_xh[4194304];
__device__ __half g_yh[4194304];
__device__ __half g_hh[16777216];
__device__ __half g_wqt[1048576];
__device__ __half g_wkt[1048576];
__device__ __half g_wvt[1048576];
__device__ __half g_w1t[4194304];
__device__ __half g_w2t[4194304];

// ---------------- PTX helpers ----------------------------------------------
__device__ __forceinline__ uint32_t smem_u32(const void* p) {
    uint32_t a;
    asm("{ .reg .u64 t; cvta.to.shared.u64 t, %1; cvt.u32.u64 %0, t; }"
        : "=r"(a) : "l"(p));
    return a;
}
__device__ __forceinline__ void cp_async16(uint32_t saddr, const void* gptr) {
    asm volatile("cp.async.ca.shared.global [%0], [%1], 16;"
                 :: "r"(saddr), "l"(gptr));
}
__device__ __forceinline__ void cp_commit() {
    asm volatile("cp.async.commit_group;");
}
template<int N>
__device__ __forceinline__ void cp_wait() {
    asm volatile("cp.async.wait_group %0;" :: "n"(N));
}
__device__ __forceinline__ void ldsm_x4(uint32_t& r0, uint32_t& r1,
                                        uint32_t& r2, uint32_t& r3, uint32_t a) {
    asm volatile("ldmatrix.sync.aligned.m8n8.x4.shared.b16 {%0,%1,%2,%3}, [%4];"
                 : "=r"(r0), "=r"(r1), "=r"(r2), "=r"(r3) : "r"(a));
}
__device__ __forceinline__ void mma_f16(float* c, const uint32_t* a,
                                        uint32_t b0, uint32_t b1) {
    asm volatile(
        "mma.sync.aligned.m16n8k16.row.col.f32.f16.f16.f32 "
        "{%0,%1,%2,%3}, {%4,%5,%6,%7}, {%8,%9}, {%0,%1,%2,%3};"
        : "+f"(c[0]), "+f"(c[1]), "+f"(c[2]), "+f"(c[3])
        : "r"(a[0]), "r"(a[1]), "r"(a[2]), "r"(a[3]), "r"(b0), "r"(b1));
}

// ---------------------------------------------------------------------------
// split: fp32 -> fp16 elementwise (vectorized by 4)
// ---------------------------------------------------------------------------
__global__ __launch_bounds__(256)
void split_kernel(const float4* __restrict__ in, __half2* __restrict__ hi, int n4)
{
    int i = blockIdx.x * 256 + threadIdx.x;
    if (i >= n4) return;
    float4 v = in[i];
    hi[2*i]   = __floats2half2_rn(v.x, v.y);
    hi[2*i+1] = __floats2half2_rn(v.z, v.w);
}

// ---------------------------------------------------------------------------
// transpose-convert: W[K,N] fp32 -> T[N,K] fp16 (32x32 smem tiles)
// ---------------------------------------------------------------------------
__global__ __launch_bounds__(256)
void tsplit_kernel(const float* __restrict__ W, __half* __restrict__ T,
                   int K, int N)
{
    __shared__ float ts[32][33];
    const int k0 = blockIdx.y << 5, n0 = blockIdx.x << 5;
    for (int i = threadIdx.x; i < 1024; i += 256) {
        int r = i >> 5, c = i & 31;
        ts[r][c] = W[(size_t)(k0 + r) * N + n0 + c];
    }
    __syncthreads();
    for (int i = threadIdx.x; i < 1024; i += 256) {
        int r = i >> 5, c = i & 31;   // r = n index, c = k index
        T[(size_t)(n0 + r) * K + k0 + c] = __float2half(ts[c][r]);
    }
}

// ---------------------------------------------------------------------------
// HMMA fp16 GEMM: out = epi(Ah[M,K] @ Bh[N,K]^T + bias)
// CTA 128x128, BK=64, 256 threads (8 warps 2x4, warp tile 64x32),
// smem row stride 72 fp16 (conflict-free ldmatrix), 3-stage cp.async pipe.
// EPI 0: (acc + bias)*scale -> (B,NH,S,HD) remap (QKV)
// EPI 1: gelu(acc + bias) -> fp16 (MLP hidden)
// EPI 2: acc + bias + res -> fp32 (final output)
// ---------------------------------------------------------------------------
#define SA_STRIDE 72
#define TILE_B    18432   // 128*72*2 bytes per array
#define STAGE_B   36864   // 2 arrays (A, B)

template<int EPI>
__global__ __launch_bounds__(256)
void mma_gemm(const __half* __restrict__ Ah, const __half* __restrict__ Bh,
              const float* __restrict__ bias, const float* __restrict__ res,
              float* __restrict__ Cf, __half* __restrict__ Ch,
              int M, int N, int K, float scale)
{
    extern __shared__ char smem[];
    const uint32_t sb = smem_u32(smem);
    const int tid = threadIdx.x, wid = tid >> 5, lane = tid & 31;
    const int m0 = blockIdx.y << 7, n0 = blockIdx.x << 7;
    const int wm = (wid >> 2) << 6;       // 0 or 64
    const int wn = (wid & 3) << 5;        // 0,32,64,96

    // ldmatrix lane addressing (element offsets)
    const int a_row = lane & 15, a_kof = (lane >> 4) << 3;
    const int b_row = ((lane >> 4) << 3) + (lane & 7), b_kof = ((lane >> 3) & 1) << 3;

    // global->smem copy mapping: row = tid>>1, chunks of 8 fp16
    const int c_row = tid >> 1, c_col = (tid & 1) << 5;

    float acc[4][4][4];
#pragma unroll
    for (int mt = 0; mt < 4; mt++)
#pragma unroll
        for (int nt = 0; nt < 4; nt++)
#pragma unroll
            for (int r = 0; r < 4; r++) acc[mt][nt][r] = 0.f;

    const int nk = K >> 6;

    auto load_tile = [&](int buf, int kt) {
        const uint32_t sbase = sb + buf * STAGE_B;
        const size_t gka = (size_t)(m0 + c_row) * K + ((size_t)kt << 6) + c_col;
        const size_t gkb = (size_t)(n0 + c_row) * K + ((size_t)kt << 6) + c_col;
        const uint32_t soff = (c_row * SA_STRIDE + c_col) * 2;
#pragma unroll
        for (int j = 0; j < 4; j++) {
            cp_async16(sbase + soff + j * 16,            Ah + gka + j * 8);
            cp_async16(sbase + TILE_B + soff + j * 16,   Bh + gkb + j * 8);
        }
        cp_commit();
    };

    load_tile(0, 0);
    load_tile(1, 1);

    for (int kt = 0; kt < nk; kt++) {
        const int buf = kt % 3;
        if (kt + 2 < nk) { load_tile((kt + 2) % 3, kt + 2); cp_wait<2>(); }
        else if (kt + 1 < nk) { cp_wait<1>(); }
        else { cp_wait<0>(); }
        __syncthreads();

        const uint32_t sA = sb + buf * STAGE_B;
        const uint32_t sB = sA + TILE_B;

#pragma unroll
        for (int ks = 0; ks < 4; ks++) {
            const int k0 = ks << 4;
            uint32_t ah[4][4];
#pragma unroll
            for (int mt = 0; mt < 4; mt++) {
                const uint32_t off =
                    ((wm + (mt << 4) + a_row) * SA_STRIDE + k0 + a_kof) * 2;
                ldsm_x4(ah[mt][0], ah[mt][1], ah[mt][2], ah[mt][3], sA + off);
            }
            uint32_t bh[4][2];
#pragma unroll
            for (int nt2 = 0; nt2 < 2; nt2++) {
                const uint32_t off =
                    ((wn + (nt2 << 4) + b_row) * SA_STRIDE + k0 + b_kof) * 2;
                uint32_t r0, r1, r2, r3;
                ldsm_x4(r0, r1, r2, r3, sB + off);
                bh[nt2*2][0] = r0; bh[nt2*2][1] = r1;
                bh[nt2*2+1][0] = r2; bh[nt2*2+1][1] = r3;
            }
#pragma unroll
            for (int mt = 0; mt < 4; mt++)
#pragma unroll
                for (int nt = 0; nt < 4; nt++)
                    mma_f16(acc[mt][nt], ah[mt], bh[nt][0], bh[nt][1]);
        }
        __syncthreads();
    }

    // ---- epilogue ----
    const int mrow_b = m0 + wm + (lane >> 2);
    const int ncol_b = n0 + wn + ((lane & 3) << 1);
#pragma unroll
    for (int mt = 0; mt < 4; mt++) {
#pragma unroll
        for (int half_ = 0; half_ < 2; half_++) {
            const int m = mrow_b + (mt << 4) + (half_ << 3);
#pragma unroll
            for (int nt = 0; nt < 4; nt++) {
                const int ncol = ncol_b + (nt << 3);
                const float b0 = bias[ncol], b1 = bias[ncol + 1];
                float o0 = acc[mt][nt][half_*2+0] + b0;
                float o1 = acc[mt][nt][half_*2+1] + b1;
                if (EPI == 0) {
                    o0 *= scale; o1 *= scale;
                    const int bi = m >> 11, ss = m & 2047;
                    const int hh = ncol >> 6, dd = ncol & 63;
                    float2* p = (float2*)&Cf[(((size_t)((bi*16 + hh)*2048 + ss)) << 6) + dd];
                    *p = make_float2(o0, o1);
                } else if (EPI == 1) {
                    const float c_ = 0.70710678118654752f;
                    float g0 = 0.5f * o0 * (1.f + erff(o0 * c_));
                    float g1 = 0.5f * o1 * (1.f + erff(o1 * c_));
                    *(__half2*)(Ch + (size_t)m * N + ncol) = __floats2half2_rn(g0, g1);
                } else {
                    const float2 r4 = *(const float2*)&res[(size_t)m * N + ncol];
                    *(float2*)&Cf[(size_t)m * N + ncol] =
                        make_float2(o0 + r4.x, o1 + r4.y);
                }
            }
        }
    }
}

// ---------------------------------------------------------------------------
// Banded attention with online softmax + global-key epilogue (R4 version,
// __expf on MUFU — exp_fast reverted, it had 2.5x worse throughput).
// ---------------------------------------------------------------------------
__global__ __launch_bounds__(256)
void attn_kernel(const float* __restrict__ Q, const float* __restrict__ Kt,
                 const float* __restrict__ Vt, const int* __restrict__ mask,
                 const float* __restrict__ bk, const float* __restrict__ bv,
                 float* __restrict__ out)
{
    extern __shared__ float sm[];
    float* Qs = sm;                 // 64x64  [d][r]
    float* Ks = sm + 4096;          // 64x64  [d][c]
    float* Vs = sm + 8192;          // 64x64  [j][d]
    float* Ps = sm + 12288;         // 64x65  [r][c]
    float* rem = sm + 12288 + 64*65;

    const int qb = blockIdx.x, h = blockIdx.y, b = blockIdx.z;
    const int qstart = qb << 6;
    const int tid = threadIdx.x, tx = tid & 15, ty = tid >> 4;
    const size_t bh = (size_t)(b * 16 + h) * 2048 * 64;
    const float* Qb = Q + bh;
    const float* Kb = Kt + bh;
    const float* Vb = Vt + bh;
    const int r0 = ty << 2, c0 = tx << 2;

    for (int i = tid; i < 1024; i += 256) {
        int r = i & 63, d4 = (i >> 6) << 2;
        float4 q4 = *(const float4*)&Qb[((size_t)(qstart + r) << 6) + d4];
        Qs[(d4+0)*64+r]=q4.x; Qs[(d4+1)*64+r]=q4.y;
        Qs[(d4+2)*64+r]=q4.z; Qs[(d4+3)*64+r]=q4.w;
    }

    float O[4][4];
    float mrow[4], lrow[4];
#pragma unroll
    for (int i = 0; i < 4; i++) {
        mrow[i] = -INFINITY; lrow[i] = 0.f;
#pragma unroll
        for (int j = 0; j < 4; j++) O[i][j] = 0.f;
    }

    for (int ch = 0; ch < 5; ch++) {
        const int jbase = qstart - 128 + (ch << 6);
        if (jbase < 0 || jbase >= 2048) continue;
        __syncthreads();
        for (int i = tid; i < 1024; i += 256) {
            int c = i & 63, d4 = (i >> 6) << 2;
            float4 k4 = *(const float4*)&Kb[((size_t)(jbase + c) << 6) + d4];
            Ks[(d4+0)*64+c]=k4.x; Ks[(d4+1)*64+c]=k4.y;
            Ks[(d4+2)*64+c]=k4.z; Ks[(d4+3)*64+c]=k4.w;
        }
        for (int i = tid; i < 1024; i += 256) {
            int j = i >> 4, d4 = (i & 15) << 2;
            *(float4*)&Vs[j * 64 + d4] = *(const float4*)&Vb[((size_t)(jbase + j) << 6) + d4];
        }
        if (tid < 64)
            rem[tid] = (mask[b * 2048 + jbase + tid] != 0) ? NEGF : 0.f;
        __syncthreads();

        float s[4][4];
#pragma unroll
        for (int i = 0; i < 4; i++)
#pragma unroll
            for (int j = 0; j < 4; j++) s[i][j] = 0.f;
#pragma unroll 8
        for (int dd = 0; dd < 64; dd++) {
            float4 a = *(const float4*)&Qs[dd * 64 + r0];
            float4 kk = *(const float4*)&Ks[dd * 64 + c0];
            float av[4] = {a.x,a.y,a.z,a.w};
            float kv[4] = {kk.x,kk.y,kk.z,kk.w};
#pragma unroll
            for (int i = 0; i < 4; i++)
#pragma unroll
                for (int j = 0; j < 4; j++)
                    s[i][j] = fmaf(av[i], kv[j], s[i][j]);
        }

#pragma unroll
        for (int i = 0; i < 4; i++) {
            float mx = -INFINITY;
#pragma unroll
            for (int j = 0; j < 4; j++) {
                int c = c0 + j, r = r0 + i;
                float sc = s[i][j] + rem[c];
                int dist = jbase + c - qstart - r;
                if (dist < -128 || dist > 128) sc = -INFINITY;
                s[i][j] = sc;
                mx = fmaxf(mx, sc);
            }
#pragma unroll
            for (int off = 8; off > 0; off >>= 1)
                mx = fmaxf(mx, __shfl_xor_sync(0xffffffffu, mx, off, 16));
            float mnew = fmaxf(mrow[i], mx);
            float corr = __expf(mrow[i] - mnew);
            mrow[i] = mnew;
            float ps = 0.f;
#pragma unroll
            for (int j = 0; j < 4; j++) {
                float p = __expf(s[i][j] - mnew);
                Ps[(r0 + i) * 65 + c0 + j] = p;
                ps += p;
            }
#pragma unroll
            for (int off = 8; off > 0; off >>= 1)
                ps += __shfl_xor_sync(0xffffffffu, ps, off, 16);
            lrow[i] = lrow[i] * corr + ps;
#pragma unroll
            for (int j = 0; j < 4; j++) O[i][j] *= corr;
        }
        __syncthreads();

#pragma unroll 8
        for (int jj = 0; jj < 64; jj++) {
            float4 vv = *(const float4*)&Vs[jj * 64 + c0];
            float pv[4] = {vv.x, vv.y, vv.z, vv.w};
#pragma unroll
            for (int i = 0; i < 4; i++) {
                float p = Ps[(r0 + i) * 65 + jj];
#pragma unroll
                for (int j = 0; j < 4; j++)
                    O[i][j] = fmaf(p, pv[j], O[i][j]);
            }
        }
    }

    const float* bkh = bk + h * 64;
    const float* bvh = bv + h * 64;
    float gp[4] = {0.f, 0.f, 0.f, 0.f};
#pragma unroll
    for (int t = 0; t < 4; t++) {
        int dd = c0 + t;
        float kbv = bkh[dd];
#pragma unroll
        for (int i = 0; i < 4; i++)
            gp[i] += Qs[dd * 64 + r0 + i] * kbv;
    }
#pragma unroll
    for (int i = 0; i < 4; i++) {
#pragma unroll
        for (int off = 8; off > 0; off >>= 1)
            gp[i] += __shfl_xor_sync(0xffffffffu, gp[i], off, 16);
        float g = gp[i];
        float mnew = fmaxf(mrow[i], g);
        float corr = __expf(mrow[i] - mnew);
        float eg = __expf(g - mnew);
        lrow[i] = lrow[i] * corr + eg;
        mrow[i] = mnew;
#pragma unroll
        for (int j = 0; j < 4; j++)
            O[i][j] = O[i][j] * corr + eg * bvh[c0 + j];
    }

#pragma unroll
    for (int i = 0; i < 4; i++) {
        int srow = qstart + r0 + i;
        int mv = mask[b * 2048 + srow];
        float inv = (mv > 0) ? 0.f : (1.f / lrow[i]);
        float4 o;
        o.x = O[i][0]*inv; o.y = O[i][1]*inv; o.z = O[i][2]*inv; o.w = O[i][3]*inv;
        *(float4*)&out[(((size_t)(b * 2048 + srow)) << 10) + (h << 6) + c0] = o;
    }
}

// ---------------------------------------------------------------------------
// y = LN(x + attn) * gamma + beta; also emits fp16 y for MLP1 input
// ---------------------------------------------------------------------------
__global__ __launch_bounds__(256)
void ln_kernel(const float* __restrict__ x, const float* __restrict__ attn,
               const float* __restrict__ gamma, const float* __restrict__ beta,
               float* __restrict__ y, __half* __restrict__ yh)
{
    __shared__ float red[8];
    __shared__ float stat;
    const int row = blockIdx.x, tid = threadIdx.x;
    const int lane = tid & 31, wid = tid >> 5;
    const float* xr = x + ((size_t)row << 10);
    const float* ar = attn + ((size_t)row << 10);
    float v[4];
#pragma unroll
    for (int i = 0; i < 4; i++) {
        int c = tid + (i << 8);
        v[i] = xr[c] + ar[c];
    }
    float s = v[0] + v[1] + v[2] + v[3];
#pragma unroll
    for (int off = 16; off > 0; off >>= 1) s += __shfl_xor_sync(~0u, s, off);
    if (lane == 0) red[wid] = s;
    __syncthreads();
    if (tid == 0) {
        float t = 0.f;
        for (int i = 0; i < 8; i++) t += red[i];
        stat = t * (1.f / 1024.f);
    }
    __syncthreads();
    const float mu = stat;
    float d2 = 0.f;
#pragma unroll
    for (int i = 0; i < 4; i++) { float d = v[i] - mu; d2 += d * d; }
#pragma unroll
    for (int off = 16; off > 0; off >>= 1) d2 += __shfl_xor_sync(~0u, d2, off);
    if (lane == 0) red[wid] = d2;
    __syncthreads();
    if (tid == 0) {
        float t = 0.f;
        for (int i = 0; i < 8; i++) t += red[i];
        stat = rsqrtf(t * (1.f / 1024.f) + 1e-5f);
    }
    __syncthreads();
    const float rs = stat;
    float* yr = y + ((size_t)row << 10);
#pragma unroll
    for (int i = 0; i < 4; i++) {
        int c = tid + (i << 8);
        float val = (v[i] - mu) * rs * gamma[c] + beta[c];
        yr[c] = val;
        yh[((size_t)row << 10) + c] = __float2half(val);
    }
}

// ---------------------------------------------------------------------------
extern "C" void kernel_launch(void* const* d_in, const int* in_sizes, int n_in,
                              void* d_out, int out_size)
{
    const float* x    = (const float*)d_in[0];
    const int*   mask = (const int*)d_in[1];
    const float* wq   = (const float*)d_in[2];
    const float* bq   = (const float*)d_in[3];
    const float* wk   = (const float*)d_in[4];
    const float* bk   = (const float*)d_in[5];
    const float* wv   = (const float*)d_in[6];
    const float* bv   = (const float*)d_in[7];
    const float* ln_g = (const float*)d_in[14];
    const float* ln_b = (const float*)d_in[15];
    const float* w1   = (const float*)d_in[16];
    const float* b1   = (const float*)d_in[17];
    const float* w2   = (const float*)d_in[18];
    const float* b2   = (const float*)d_in[19];

    float *q, *k, *v, *attn, *y;
    __half *xh, *yh, *hh, *wqt, *wkt, *wvt, *w1t, *w2t;
    cudaGetSymbolAddress((void**)&q,    g_q);
    cudaGetSymbolAddress((void**)&k,    g_k);
    cudaGetSymbolAddress((void**)&v,    g_v);
    cudaGetSymbolAddress((void**)&attn, g_attn);
    cudaGetSymbolAddress((void**)&y,    g_y);
    cudaGetSymbolAddress((void**)&xh,   g_xh);
    cudaGetSymbolAddress((void**)&yh,   g_yh);
    cudaGetSymbolAddress((void**)&hh,   g_hh);
    cudaGetSymbolAddress((void**)&wqt,  g_wqt);
    cudaGetSymbolAddress((void**)&wkt,  g_wkt);
    cudaGetSymbolAddress((void**)&wvt,  g_wvt);
    cudaGetSymbolAddress((void**)&w1t,  g_w1t);
    cudaGetSymbolAddress((void**)&w2t,  g_w2t);

    const int ATT_SMEM = (64*64*3 + 64*65 + 64) * 4;  // 66048 B
    const int G_SMEM = 3 * STAGE_B;                   // 110592 B
    cudaFuncSetAttribute(attn_kernel,
                         cudaFuncAttributeMaxDynamicSharedMemorySize, ATT_SMEM);
    cudaFuncSetAttribute(mma_gemm<0>,
                         cudaFuncAttributeMaxDynamicSharedMemorySize, G_SMEM);
    cudaFuncSetAttribute(mma_gemm<1>,
                         cudaFuncAttributeMaxDynamicSharedMemorySize, G_SMEM);
    cudaFuncSetAttribute(mma_gemm<2>,
                         cudaFuncAttributeMaxDynamicSharedMemorySize, G_SMEM);

    // input / weight conversion
    split_kernel<<<4096, 256>>>((const float4*)x, (__half2*)xh, 1048576);
    tsplit_kernel<<<dim3(32, 32),  256>>>(wq, wqt, 1024, 1024);
    tsplit_kernel<<<dim3(32, 32),  256>>>(wk, wkt, 1024, 1024);
    tsplit_kernel<<<dim3(32, 32),  256>>>(wv, wvt, 1024, 1024);
    tsplit_kernel<<<dim3(128, 32), 256>>>(w1, w1t, 1024, 4096);
    tsplit_kernel<<<dim3(32, 128), 256>>>(w2, w2t, 4096, 1024);

    // QKV projections (HMMA)
    mma_gemm<0><<<dim3(8, 32), 256, G_SMEM>>>(xh, wqt, bq, nullptr,
                                              q, nullptr, 4096, 1024, 1024, 0.125f);
    mma_gemm<0><<<dim3(8, 32), 256, G_SMEM>>>(xh, wkt, bk, nullptr,
                                              k, nullptr, 4096, 1024, 1024, 1.0f);
    mma_gemm<0><<<dim3(8, 32), 256, G_SMEM>>>(xh, wvt, bv, nullptr,
                                              v, nullptr, 4096, 1024, 1024, 1.0f);
    // banded attention + global key
    attn_kernel<<<dim3(32, 16, 2), 256, ATT_SMEM>>>(q, k, v, mask, bk, bv, attn);
    // residual add + layernorm (emits fp32 + fp16)
    ln_kernel<<<4096, 256>>>(x, attn, ln_g, ln_b, y, yh);
    // MLP
    mma_gemm<1><<<dim3(32, 32), 256, G_SMEM>>>(yh, w1t, b1, nullptr,
                                               nullptr, hh, 4096, 4096, 1024, 1.0f);
    mma_gemm<2><<<dim3(8, 32), 256, G_SMEM>>>(hh, w2t, b2, y,
                                              (float*)d_out, nullptr, 4096, 1024, 4096, 1.0f);
}

// round 11
// speedup vs baseline: 1.6605x; 1.6605x over previous
#include <cuda_runtime.h>
#include <cuda_fp16.h>
#include <math.h>
#include <stdint.h>

// ---------------------------------------------------------------------------
// HFLongFormerSelfAttentionBlock on GB300 (sm_103 base PTX target -> mma.sync)
// R7: 1-term fp16 GEMM (as R6) but 4-stage cp.async pipeline -> 147456B smem
//     -> forces 1 CTA/SM (R6's 2 CTA/SM L1tex contention hypothesis).
//     Launch order shuffled so ncu (-s 5 -c 1) captures the Q-projection GEMM.
// ---------------------------------------------------------------------------

#define NEGF (-3.4028234663852886e38f)

// ---------------- scratch (device globals; no allocation allowed) ----------
__device__ float g_q[4194304];     // (B,NH,S0,HD)
__device__ float g_k[4194304];
__device__ float g_v[4194304];
__device__ float g_attn[4194304];  // (B*S0, H)
__device__ float g_y[4194304];     // LN output fp32
__device__ __half g_xh[4194304];
__device__ __half g_yh[4194304];
__device__ __half g_hh[16777216];
__device__ __half g_wqt[1048576];
__device__ __half g_wkt[1048576];
__device__ __half g_wvt[1048576];
__device__ __half g_w1t[4194304];
__device__ __half g_w2t[4194304];

// ---------------- PTX helpers ----------------------------------------------
__device__ __forceinline__ uint32_t smem_u32(const void* p) {
    uint32_t a;
    asm("{ .reg .u64 t; cvta.to.shared.u64 t, %1; cvt.u32.u64 %0, t; }"
        : "=r"(a) : "l"(p));
    return a;
}
__device__ __forceinline__ void cp_async16(uint32_t saddr, const void* gptr) {
    asm volatile("cp.async.ca.shared.global [%0], [%1], 16;"
                 :: "r"(saddr), "l"(gptr));
}
__device__ __forceinline__ void cp_commit() {
    asm volatile("cp.async.commit_group;");
}
template<int N>
__device__ __forceinline__ void cp_wait() {
    asm volatile("cp.async.wait_group %0;" :: "n"(N));
}
__device__ __forceinline__ void ldsm_x4(uint32_t& r0, uint32_t& r1,
                                        uint32_t& r2, uint32_t& r3, uint32_t a) {
    asm volatile("ldmatrix.sync.aligned.m8n8.x4.shared.b16 {%0,%1,%2,%3}, [%4];"
                 : "=r"(r0), "=r"(r1), "=r"(r2), "=r"(r3) : "r"(a));
}
__device__ __forceinline__ void mma_f16(float* c, const uint32_t* a,
                                        uint32_t b0, uint32_t b1) {
    asm volatile(
        "mma.sync.aligned.m16n8k16.row.col.f32.f16.f16.f32 "
        "{%0,%1,%2,%3}, {%4,%5,%6,%7}, {%8,%9}, {%0,%1,%2,%3};"
        : "+f"(c[0]), "+f"(c[1]), "+f"(c[2]), "+f"(c[3])
        : "r"(a[0]), "r"(a[1]), "r"(a[2]), "r"(a[3]), "r"(b0), "r"(b1));
}

// ---------------------------------------------------------------------------
// split: fp32 -> fp16 elementwise (vectorized by 4)
// ---------------------------------------------------------------------------
__global__ __launch_bounds__(256)
void split_kernel(const float4* __restrict__ in, __half2* __restrict__ hi, int n4)
{
    int i = blockIdx.x * 256 + threadIdx.x;
    if (i >= n4) return;
    float4 v = in[i];
    hi[2*i]   = __floats2half2_rn(v.x, v.y);
    hi[2*i+1] = __floats2half2_rn(v.z, v.w);
}

// ---------------------------------------------------------------------------
// transpose-convert: W[K,N] fp32 -> T[N,K] fp16 (32x32 smem tiles)
// ---------------------------------------------------------------------------
__global__ __launch_bounds__(256)
void tsplit_kernel(const float* __restrict__ W, __half* __restrict__ T,
                   int K, int N)
{
    __shared__ float ts[32][33];
    const int k0 = blockIdx.y << 5, n0 = blockIdx.x << 5;
    for (int i = threadIdx.x; i < 1024; i += 256) {
        int r = i >> 5, c = i & 31;
        ts[r][c] = W[(size_t)(k0 + r) * N + n0 + c];
    }
    __syncthreads();
    for (int i = threadIdx.x; i < 1024; i += 256) {
        int r = i >> 5, c = i & 31;   // r = n index, c = k index
        T[(size_t)(n0 + r) * K + k0 + c] = __float2half(ts[c][r]);
    }
}

// ---------------------------------------------------------------------------
// HMMA fp16 GEMM: out = epi(Ah[M,K] @ Bh[N,K]^T + bias)
// CTA 128x128, BK=64, 256 threads (8 warps 2x4, warp tile 64x32),
// smem row stride 72 fp16 (conflict-free ldmatrix), 4-stage cp.async pipe
// (147456 B dynamic smem -> exactly 1 CTA/SM).
// EPI 0: (acc + bias)*scale -> (B,NH,S,HD) remap (QKV)
// EPI 1: gelu(acc + bias) -> fp16 (MLP hidden)
// EPI 2: acc + bias + res -> fp32 (final output)
// ---------------------------------------------------------------------------
#define SA_STRIDE 72
#define TILE_B    18432   // 128*72*2 bytes per array
#define STAGE_B   36864   // 2 arrays (A, B)
#define NSTAGE    4

template<int EPI>
__global__ __launch_bounds__(256)
void mma_gemm(const __half* __restrict__ Ah, const __half* __restrict__ Bh,
              const float* __restrict__ bias, const float* __restrict__ res,
              float* __restrict__ Cf, __half* __restrict__ Ch,
              int M, int N, int K, float scale)
{
    extern __shared__ char smem[];
    const uint32_t sb = smem_u32(smem);
    const int tid = threadIdx.x, wid = tid >> 5, lane = tid & 31;
    const int m0 = blockIdx.y << 7, n0 = blockIdx.x << 7;
    const int wm = (wid >> 2) << 6;       // 0 or 64
    const int wn = (wid & 3) << 5;        // 0,32,64,96

    // ldmatrix lane addressing (element offsets)
    const int a_row = lane & 15, a_kof = (lane >> 4) << 3;
    const int b_row = ((lane >> 4) << 3) + (lane & 7), b_kof = ((lane >> 3) & 1) << 3;

    // global->smem copy mapping: row = tid>>1, chunks of 8 fp16
    const int c_row = tid >> 1, c_col = (tid & 1) << 5;

    float acc[4][4][4];
#pragma unroll
    for (int mt = 0; mt < 4; mt++)
#pragma unroll
        for (int nt = 0; nt < 4; nt++)
#pragma unroll
            for (int r = 0; r < 4; r++) acc[mt][nt][r] = 0.f;

    const int nk = K >> 6;

    auto load_tile = [&](int buf, int kt) {
        const uint32_t sbase = sb + buf * STAGE_B;
        const size_t gka = (size_t)(m0 + c_row) * K + ((size_t)kt << 6) + c_col;
        const size_t gkb = (size_t)(n0 + c_row) * K + ((size_t)kt << 6) + c_col;
        const uint32_t soff = (c_row * SA_STRIDE + c_col) * 2;
#pragma unroll
        for (int j = 0; j < 4; j++) {
            cp_async16(sbase + soff + j * 16,            Ah + gka + j * 8);
            cp_async16(sbase + TILE_B + soff + j * 16,   Bh + gkb + j * 8);
        }
        cp_commit();
    };

    load_tile(0, 0);
    load_tile(1, 1);
    load_tile(2, 2);

    for (int kt = 0; kt < nk; kt++) {
        const int buf = kt & (NSTAGE - 1);
        if (kt + 3 < nk)      { load_tile((kt + 3) & (NSTAGE - 1), kt + 3); cp_wait<3>(); }
        else if (kt + 2 < nk) { cp_wait<2>(); }
        else if (kt + 1 < nk) { cp_wait<1>(); }
        else                  { cp_wait<0>(); }
        __syncthreads();

        const uint32_t sA = sb + buf * STAGE_B;
        const uint32_t sB = sA + TILE_B;

#pragma unroll
        for (int ks = 0; ks < 4; ks++) {
            const int k0 = ks << 4;
            uint32_t ah[4][4];
#pragma unroll
            for (int mt = 0; mt < 4; mt++) {
                const uint32_t off =
                    ((wm + (mt << 4) + a_row) * SA_STRIDE + k0 + a_kof) * 2;
                ldsm_x4(ah[mt][0], ah[mt][1], ah[mt][2], ah[mt][3], sA + off);
            }
            uint32_t bh[4][2];
#pragma unroll
            for (int nt2 = 0; nt2 < 2; nt2++) {
                const uint32_t off =
                    ((wn + (nt2 << 4) + b_row) * SA_STRIDE + k0 + b_kof) * 2;
                uint32_t r0, r1, r2, r3;
                ldsm_x4(r0, r1, r2, r3, sB + off);
                bh[nt2*2][0] = r0; bh[nt2*2][1] = r1;
                bh[nt2*2+1][0] = r2; bh[nt2*2+1][1] = r3;
            }
#pragma unroll
            for (int mt = 0; mt < 4; mt++)
#pragma unroll
                for (int nt = 0; nt < 4; nt++)
                    mma_f16(acc[mt][nt], ah[mt], bh[nt][0], bh[nt][1]);
        }
        __syncthreads();
    }

    // ---- epilogue ----
    const int mrow_b = m0 + wm + (lane >> 2);
    const int ncol_b = n0 + wn + ((lane & 3) << 1);
#pragma unroll
    for (int mt = 0; mt < 4; mt++) {
#pragma unroll
        for (int half_ = 0; half_ < 2; half_++) {
            const int m = mrow_b + (mt << 4) + (half_ << 3);
#pragma unroll
            for (int nt = 0; nt < 4; nt++) {
                const int ncol = ncol_b + (nt << 3);
                const float b0 = bias[ncol], b1 = bias[ncol + 1];
                float o0 = acc[mt][nt][half_*2+0] + b0;
                float o1 = acc[mt][nt][half_*2+1] + b1;
                if (EPI == 0) {
                    o0 *= scale; o1 *= scale;
                    const int bi = m >> 11, ss = m & 2047;
                    const int hh = ncol >> 6, dd = ncol & 63;
                    float2* p = (float2*)&Cf[(((size_t)((bi*16 + hh)*2048 + ss)) << 6) + dd];
                    *p = make_float2(o0, o1);
                } else if (EPI == 1) {
                    const float c_ = 0.70710678118654752f;
                    float g0 = 0.5f * o0 * (1.f + erff(o0 * c_));
                    float g1 = 0.5f * o1 * (1.f + erff(o1 * c_));
                    *(__half2*)(Ch + (size_t)m * N + ncol) = __floats2half2_rn(g0, g1);
                } else {
                    const float2 r4 = *(const float2*)&res[(size_t)m * N + ncol];
                    *(float2*)&Cf[(size_t)m * N + ncol] =
                        make_float2(o0 + r4.x, o1 + r4.y);
                }
            }
        }
    }
}

// ---------------------------------------------------------------------------
// Banded attention with online softmax + global-key epilogue (__expf / MUFU)
// ---------------------------------------------------------------------------
__global__ __launch_bounds__(256)
void attn_kernel(const float* __restrict__ Q, const float* __restrict__ Kt,
                 const float* __restrict__ Vt, const int* __restrict__ mask,
                 const float* __restrict__ bk, const float* __restrict__ bv,
                 float* __restrict__ out)
{
    extern __shared__ float sm[];
    float* Qs = sm;                 // 64x64  [d][r]
    float* Ks = sm + 4096;          // 64x64  [d][c]
    float* Vs = sm + 8192;          // 64x64  [j][d]
    float* Ps = sm + 12288;         // 64x65  [r][c]
    float* rem = sm + 12288 + 64*65;

    const int qb = blockIdx.x, h = blockIdx.y, b = blockIdx.z;
    const int qstart = qb << 6;
    const int tid = threadIdx.x, tx = tid & 15, ty = tid >> 4;
    const size_t bh = (size_t)(b * 16 + h) * 2048 * 64;
    const float* Qb = Q + bh;
    const float* Kb = Kt + bh;
    const float* Vb = Vt + bh;
    const int r0 = ty << 2, c0 = tx << 2;

    for (int i = tid; i < 1024; i += 256) {
        int r = i & 63, d4 = (i >> 6) << 2;
        float4 q4 = *(const float4*)&Qb[((size_t)(qstart + r) << 6) + d4];
        Qs[(d4+0)*64+r]=q4.x; Qs[(d4+1)*64+r]=q4.y;
        Qs[(d4+2)*64+r]=q4.z; Qs[(d4+3)*64+r]=q4.w;
    }

    float O[4][4];
    float mrow[4], lrow[4];
#pragma unroll
    for (int i = 0; i < 4; i++) {
        mrow[i] = -INFINITY; lrow[i] = 0.f;
#pragma unroll
        for (int j = 0; j < 4; j++) O[i][j] = 0.f;
    }

    for (int ch = 0; ch < 5; ch++) {
        const int jbase = qstart - 128 + (ch << 6);
        if (jbase < 0 || jbase >= 2048) continue;
        __syncthreads();
        for (int i = tid; i < 1024; i += 256) {
            int c = i & 63, d4 = (i >> 6) << 2;
            float4 k4 = *(const float4*)&Kb[((size_t)(jbase + c) << 6) + d4];
            Ks[(d4+0)*64+c]=k4.x; Ks[(d4+1)*64+c]=k4.y;
            Ks[(d4+2)*64+c]=k4.z; Ks[(d4+3)*64+c]=k4.w;
        }
        for (int i = tid; i < 1024; i += 256) {
            int j = i >> 4, d4 = (i & 15) << 2;
            *(float4*)&Vs[j * 64 + d4] = *(const float4*)&Vb[((size_t)(jbase + j) << 6) + d4];
        }
        if (tid < 64)
            rem[tid] = (mask[b * 2048 + jbase + tid] != 0) ? NEGF : 0.f;
        __syncthreads();

        float s[4][4];
#pragma unroll
        for (int i = 0; i < 4; i++)
#pragma unroll
            for (int j = 0; j < 4; j++) s[i][j] = 0.f;
#pragma unroll 8
        for (int dd = 0; dd < 64; dd++) {
            float4 a = *(const float4*)&Qs[dd * 64 + r0];
            float4 kk = *(const float4*)&Ks[dd * 64 + c0];
            float av[4] = {a.x,a.y,a.z,a.w};
            float kv[4] = {kk.x,kk.y,kk.z,kk.w};
#pragma unroll
            for (int i = 0; i < 4; i++)
#pragma unroll
                for (int j = 0; j < 4; j++)
                    s[i][j] = fmaf(av[i], kv[j], s[i][j]);
        }

#pragma unroll
        for (int i = 0; i < 4; i++) {
            float mx = -INFINITY;
#pragma unroll
            for (int j = 0; j < 4; j++) {
                int c = c0 + j, r = r0 + i;
                float sc = s[i][j] + rem[c];
                int dist = jbase + c - qstart - r;
                if (dist < -128 || dist > 128) sc = -INFINITY;
                s[i][j] = sc;
                mx = fmaxf(mx, sc);
            }
#pragma unroll
            for (int off = 8; off > 0; off >>= 1)
                mx = fmaxf(mx, __shfl_xor_sync(0xffffffffu, mx, off, 16));
            float mnew = fmaxf(mrow[i], mx);
            float corr = __expf(mrow[i] - mnew);
            mrow[i] = mnew;
            float ps = 0.f;
#pragma unroll
            for (int j = 0; j < 4; j++) {
                float p = __expf(s[i][j] - mnew);
                Ps[(r0 + i) * 65 + c0 + j] = p;
                ps += p;
            }
#pragma unroll
            for (int off = 8; off > 0; off >>= 1)
                ps += __shfl_xor_sync(0xffffffffu, ps, off, 16);
            lrow[i] = lrow[i] * corr + ps;
#pragma unroll
            for (int j = 0; j < 4; j++) O[i][j] *= corr;
        }
        __syncthreads();

#pragma unroll 8
        for (int jj = 0; jj < 64; jj++) {
            float4 vv = *(const float4*)&Vs[jj * 64 + c0];
            float pv[4] = {vv.x, vv.y, vv.z, vv.w};
#pragma unroll
            for (int i = 0; i < 4; i++) {
                float p = Ps[(r0 + i) * 65 + jj];
#pragma unroll
                for (int j = 0; j < 4; j++)
                    O[i][j] = fmaf(p, pv[j], O[i][j]);
            }
        }
    }

    const float* bkh = bk + h * 64;
    const float* bvh = bv + h * 64;
    float gp[4] = {0.f, 0.f, 0.f, 0.f};
#pragma unroll
    for (int t = 0; t < 4; t++) {
        int dd = c0 + t;
        float kbv = bkh[dd];
#pragma unroll
        for (int i = 0; i < 4; i++)
            gp[i] += Qs[dd * 64 + r0 + i] * kbv;
    }
#pragma unroll
    for (int i = 0; i < 4; i++) {
#pragma unroll
        for (int off = 8; off > 0; off >>= 1)
            gp[i] += __shfl_xor_sync(0xffffffffu, gp[i], off, 16);
        float g = gp[i];
        float mnew = fmaxf(mrow[i], g);
        float corr = __expf(mrow[i] - mnew);
        float eg = __expf(g - mnew);
        lrow[i] = lrow[i] * corr + eg;
        mrow[i] = mnew;
#pragma unroll
        for (int j = 0; j < 4; j++)
            O[i][j] = O[i][j] * corr + eg * bvh[c0 + j];
    }

#pragma unroll
    for (int i = 0; i < 4; i++) {
        int srow = qstart + r0 + i;
        int mv = mask[b * 2048 + srow];
        float inv = (mv > 0) ? 0.f : (1.f / lrow[i]);
        float4 o;
        o.x = O[i][0]*inv; o.y = O[i][1]*inv; o.z = O[i][2]*inv; o.w = O[i][3]*inv;
        *(float4*)&out[(((size_t)(b * 2048 + srow)) << 10) + (h << 6) + c0] = o;
    }
}

// ---------------------------------------------------------------------------
// y = LN(x + attn) * gamma + beta; also emits fp16 y for MLP1 input
// ---------------------------------------------------------------------------
__global__ __launch_bounds__(256)
void ln_kernel(const float* __restrict__ x, const float* __restrict__ attn,
               const float* __restrict__ gamma, const float* __restrict__ beta,
               float* __restrict__ y, __half* __restrict__ yh)
{
    __shared__ float red[8];
    __shared__ float stat;
    const int row = blockIdx.x, tid = threadIdx.x;
    const int lane = tid & 31, wid = tid >> 5;
    const float* xr = x + ((size_t)row << 10);
    const float* ar = attn + ((size_t)row << 10);
    float v[4];
#pragma unroll
    for (int i = 0; i < 4; i++) {
        int c = tid + (i << 8);
        v[i] = xr[c] + ar[c];
    }
    float s = v[0] + v[1] + v[2] + v[3];
#pragma unroll
    for (int off = 16; off > 0; off >>= 1) s += __shfl_xor_sync(~0u, s, off);
    if (lane == 0) red[wid] = s;
    __syncthreads();
    if (tid == 0) {
        float t = 0.f;
        for (int i = 0; i < 8; i++) t += red[i];
        stat = t * (1.f / 1024.f);
    }
    __syncthreads();
    const float mu = stat;
    float d2 = 0.f;
#pragma unroll
    for (int i = 0; i < 4; i++) { float d = v[i] - mu; d2 += d * d; }
#pragma unroll
    for (int off = 16; off > 0; off >>= 1) d2 += __shfl_xor_sync(~0u, d2, off);
    if (lane == 0) red[wid] = d2;
    __syncthreads();
    if (tid == 0) {
        float t = 0.f;
        for (int i = 0; i < 8; i++) t += red[i];
        stat = rsqrtf(t * (1.f / 1024.f) + 1e-5f);
    }
    __syncthreads();
    const float rs = stat;
    float* yr = y + ((size_t)row << 10);
#pragma unroll
    for (int i = 0; i < 4; i++) {
        int c = tid + (i << 8);
        float val = (v[i] - mu) * rs * gamma[c] + beta[c];
        yr[c] = val;
        yh[((size_t)row << 10) + c] = __float2half(val);
    }
}

// ---------------------------------------------------------------------------
extern "C" void kernel_launch(void* const* d_in, const int* in_sizes, int n_in,
                              void* d_out, int out_size)
{
    const float* x    = (const float*)d_in[0];
    const int*   mask = (const int*)d_in[1];
    const float* wq   = (const float*)d_in[2];
    const float* bq   = (const float*)d_in[3];
    const float* wk   = (const float*)d_in[4];
    const float* bk   = (const float*)d_in[5];
    const float* wv   = (const float*)d_in[6];
    const float* bv   = (const float*)d_in[7];
    const float* ln_g = (const float*)d_in[14];
    const float* ln_b = (const float*)d_in[15];
    const float* w1   = (const float*)d_in[16];
    const float* b1   = (const float*)d_in[17];
    const float* w2   = (const float*)d_in[18];
    const float* b2   = (const float*)d_in[19];

    float *q, *k, *v, *attn, *y;
    __half *xh, *yh, *hh, *wqt, *wkt, *wvt, *w1t, *w2t;
    cudaGetSymbolAddress((void**)&q,    g_q);
    cudaGetSymbolAddress((void**)&k,    g_k);
    cudaGetSymbolAddress((void**)&v,    g_v);
    cudaGetSymbolAddress((void**)&attn, g_attn);
    cudaGetSymbolAddress((void**)&y,    g_y);
    cudaGetSymbolAddress((void**)&xh,   g_xh);
    cudaGetSymbolAddress((void**)&yh,   g_yh);
    cudaGetSymbolAddress((void**)&hh,   g_hh);
    cudaGetSymbolAddress((void**)&wqt,  g_wqt);
    cudaGetSymbolAddress((void**)&wkt,  g_wkt);
    cudaGetSymbolAddress((void**)&wvt,  g_wvt);
    cudaGetSymbolAddress((void**)&w1t,  g_w1t);
    cudaGetSymbolAddress((void**)&w2t,  g_w2t);

    const int ATT_SMEM = (64*64*3 + 64*65 + 64) * 4;  // 66048 B
    const int G_SMEM = NSTAGE * STAGE_B;              // 147456 B -> 1 CTA/SM
    cudaFuncSetAttribute(attn_kernel,
                         cudaFuncAttributeMaxDynamicSharedMemorySize, ATT_SMEM);
    cudaFuncSetAttribute(mma_gemm<0>,
                         cudaFuncAttributeMaxDynamicSharedMemorySize, G_SMEM);
    cudaFuncSetAttribute(mma_gemm<1>,
                         cudaFuncAttributeMaxDynamicSharedMemorySize, G_SMEM);
    cudaFuncSetAttribute(mma_gemm<2>,
                         cudaFuncAttributeMaxDynamicSharedMemorySize, G_SMEM);

    // conversions (5 launches) then gemmQ as launch #6 -> ncu -s5 -c1 lands on it
    split_kernel<<<4096, 256>>>((const float4*)x, (__half2*)xh, 1048576);
    tsplit_kernel<<<dim3(32, 32),  256>>>(wq, wqt, 1024, 1024);
    tsplit_kernel<<<dim3(32, 32),  256>>>(wk, wkt, 1024, 1024);
    tsplit_kernel<<<dim3(32, 32),  256>>>(wv, wvt, 1024, 1024);
    tsplit_kernel<<<dim3(128, 32), 256>>>(w1, w1t, 1024, 4096);
    // launch #6:
    mma_gemm<0><<<dim3(8, 32), 256, G_SMEM>>>(xh, wqt, bq, nullptr,
                                              q, nullptr, 4096, 1024, 1024, 0.125f);
    tsplit_kernel<<<dim3(32, 128), 256>>>(w2, w2t, 4096, 1024);
    mma_gemm<0><<<dim3(8, 32), 256, G_SMEM>>>(xh, wkt, bk, nullptr,
                                              k, nullptr, 4096, 1024, 1024, 1.0f);
    mma_gemm<0><<<dim3(8, 32), 256, G_SMEM>>>(xh, wvt, bv, nullptr,
                                              v, nullptr, 4096, 1024, 1024, 1.0f);
    // banded attention + global key
    attn_kernel<<<dim3(32, 16, 2), 256, ATT_SMEM>>>(q, k, v, mask, bk, bv, attn);
    // residual add + layernorm (emits fp32 + fp16)
    ln_kernel<<<4096, 256>>>(x, attn, ln_g, ln_b, y, yh);
    // MLP
    mma_gemm<1><<<dim3(32, 32), 256, G_SMEM>>>(yh, w1t, b1, nullptr,
                                               nullptr, hh, 4096, 4096, 1024, 1.0f);
    mma_gemm<2><<<dim3(8, 32), 256, G_SMEM>>>(hh, w2t, b2, y,
                                              (float*)d_out, nullptr, 4096, 1024, 4096, 1.0f);
}